// round 11
// baseline (speedup 1.0000x reference)
#include <cuda_runtime.h>
#include <cstdint>

#define NN 100000
#define NE 1600000
#define GNUM 128
#define OUT_CH 10

typedef unsigned long long u64;

// ---------------- device scratch ----------------
__device__ int   g_deg[NN];
__device__ int   g_rowptr[NN + 1];
__device__ int   g_cursor[NN];
__device__ int   g_esrc[NE];
__device__ int   g_bsum[128];
__device__ float g_y[(size_t)NN * 64];
__device__ float g_y2[(size_t)NN * 64];
__device__ float g_pcat[GNUM * 256];            // k = layer*64 + c
__device__ int   g_cnt[GNUM];
__device__ float g_pooled[GNUM * 64];

// ---------------- f32x2 helpers ----------------
__device__ __forceinline__ u64 pack2(float lo, float hi) {
    u64 r; asm("mov.b64 %0, {%1, %2};" : "=l"(r) : "f"(lo), "f"(hi)); return r;
}
__device__ __forceinline__ u64 dup2(float v) {
    u64 r; asm("mov.b64 %0, {%1, %1};" : "=l"(r) : "f"(v)); return r;
}
__device__ __forceinline__ void fma2(u64& d, u64 a, u64 b) {
    asm("fma.rn.f32x2 %0, %1, %2, %0;" : "+l"(d) : "l"(a), "l"(b));
}
__device__ __forceinline__ float2 unpack2(u64 v) {
    float2 f; asm("mov.b64 {%0, %1}, %2;" : "=f"(f.x), "=f"(f.y) : "l"(v)); return f;
}
__device__ __forceinline__ void red_f32(float* p, float v) {
    asm volatile("red.global.add.f32 [%0], %1;" :: "l"(p), "f"(v) : "memory");
}

// ---------------- CSR build ----------------
__global__ void hist_kernel(const int* __restrict__ ei) {
    int e = blockIdx.x * blockDim.x + threadIdx.x;
    if (e < NE) atomicAdd(&g_deg[ei[NE + e]], 1);
}

__global__ void scan1_kernel() {
    __shared__ int wsum[8];
    int tid = threadIdx.x;
    int base = blockIdx.x * 1024 + tid * 4;
    int v[4];
#pragma unroll
    for (int i = 0; i < 4; i++) v[i] = (base + i < NN) ? g_deg[base + i] : 0;
    int s = v[0] + v[1] + v[2] + v[3];
    int lane = tid & 31, w = tid >> 5;
    int inc = s;
    for (int o = 1; o < 32; o <<= 1) {
        int t = __shfl_up_sync(0xffffffffu, inc, o);
        if (lane >= o) inc += t;
    }
    if (lane == 31) wsum[w] = inc;
    __syncthreads();
    if (tid < 8) {
        int x = wsum[tid];
        int inc2 = x;
        for (int o = 1; o < 8; o <<= 1) {
            int t = __shfl_up_sync(0xffu, inc2, o);
            if (tid >= o) inc2 += t;
        }
        wsum[tid] = inc2 - x;
        if (tid == 7) g_bsum[blockIdx.x] = inc2;
    }
    __syncthreads();
    int run = wsum[w] + inc - s;
#pragma unroll
    for (int i = 0; i < 4; i++) {
        if (base + i < NN) g_deg[base + i] = run;
        run += v[i];
    }
}

__global__ void scan2_kernel(int nb) {
    __shared__ int ws[4];
    int tid = threadIdx.x;
    int v = (tid < nb) ? g_bsum[tid] : 0;
    int lane = tid & 31, w = tid >> 5;
    int inc = v;
    for (int o = 1; o < 32; o <<= 1) {
        int t = __shfl_up_sync(0xffffffffu, inc, o);
        if (lane >= o) inc += t;
    }
    if (lane == 31) ws[w] = inc;
    __syncthreads();
    int add = 0;
    for (int i = 0; i < w; i++) add += ws[i];
    if (tid < nb) g_bsum[tid] = add + inc - v;
}

__global__ void scan3_kernel() {
    int tid = threadIdx.x;
    int base = blockIdx.x * 1024 + tid * 4;
    int add = g_bsum[blockIdx.x];
#pragma unroll
    for (int i = 0; i < 4; i++) {
        int idx = base + i;
        if (idx < NN) {
            int r = g_deg[idx] + add;
            g_rowptr[idx] = r;
            g_cursor[idx] = r;
        }
    }
    if (blockIdx.x == 0 && tid == 0) g_rowptr[NN] = NE;
}

__global__ void fill_kernel(const int* __restrict__ ei) {
    int e = blockIdx.x * blockDim.x + threadIdx.x;
    if (e < NE) {
        int d = ei[NE + e];
        int p = atomicAdd(&g_cursor[d], 1);
        g_esrc[p] = ei[e];
    }
}

// ---------------- graph counts ----------------
__global__ void cnt_kernel(const int* __restrict__ batch) {
    __shared__ int h[GNUM];
    int tid = threadIdx.x;
    if (tid < GNUM) h[tid] = 0;
    __syncthreads();
    int i = blockIdx.x * 256 + tid;
    if (i < NN) atomicAdd(&h[batch[i]], 1);
    __syncthreads();
    if (tid < GNUM && h[tid]) atomicAdd(&g_cnt[tid], h[tid]);
}

// ---------------- y0 = x @ W1f (K=128 -> 64), f32x2 ----------------
__global__ void __launch_bounds__(256) gemm_y0_kernel(
    const float* __restrict__ x, const float* __restrict__ W)
{
    extern __shared__ float sm[];
    float* zs = sm;            // [128][65]
    float* ws = zs + 128 * 65; // [128][64]
    int tid = threadIdx.x;
    int node0 = blockIdx.x * 64;

    for (int i = tid; i < 128 * 64; i += 256) ws[i] = W[i];
    for (int i = tid; i < 2048; i += 256) {     // 64 nodes x 32 float4
        int n = i >> 5, kq = i & 31;
        int gn = node0 + n;
        float4 v = (gn < NN) ? *(const float4*)(x + (size_t)gn * 128 + kq * 4)
                             : make_float4(0.f, 0.f, 0.f, 0.f);
        zs[(4 * kq + 0) * 65 + n] = v.x;
        zs[(4 * kq + 1) * 65 + n] = v.y;
        zs[(4 * kq + 2) * 65 + n] = v.z;
        zs[(4 * kq + 3) * 65 + n] = v.w;
    }
    __syncthreads();

    int n = tid & 63, grp = tid >> 6, cb = grp * 16;
    u64 acc[8];
#pragma unroll
    for (int j = 0; j < 8; j++) acc[j] = 0ull;
    for (int k = 0; k < 128; k++) {
        u64 zz = dup2(zs[k * 65 + n]);
        const ulonglong2* wr = (const ulonglong2*)&ws[k * 64 + cb];
#pragma unroll
        for (int j = 0; j < 4; j++) {
            ulonglong2 w = wr[j];
            fma2(acc[2 * j], zz, w.x);
            fma2(acc[2 * j + 1], zz, w.y);
        }
    }
    int gn = node0 + n;
    if (gn < NN) {
        float4* o = (float4*)(g_y + (size_t)gn * 64 + cb);
#pragma unroll
        for (int j = 0; j < 4; j++) {
            float2 a = unpack2(acc[2 * j]);
            float2 b = unpack2(acc[2 * j + 1]);
            o[j] = make_float4(a.x, a.y, b.x, b.y);
        }
    }
}

// -------- fused layer: gather z = relu(y + Σ y[src] + b1); h = relu(z@W2+b2);
//          pool h per-graph into pcat; yout = h@W1n (if SECOND; yout != y) --------
template<bool SECOND>
__global__ void __launch_bounds__(256) layer_kernel(
    const float* __restrict__ y,
    const float* __restrict__ b1,
    const float* __restrict__ W2, const float* __restrict__ b2,
    const int* __restrict__ batch, int layer,
    const float* __restrict__ W1n, float* __restrict__ yout)
{
    extern __shared__ float sm[];
    float* zs = sm;              // [64][65]  (z transposed [k][n])
    float* w2 = zs + 64 * 65;    // [64][64]
    float* hs = w2 + 4096;       // [64][65]  (h transposed [c][n])
    float* w1 = hs + 64 * 65;    // [64][64]
    int*   sb = (int*)(w1 + 4096); // [64] batch ids
    int tid = threadIdx.x;
    int node0 = blockIdx.x * 64;
    int nmax = min(64, NN - node0);

    for (int i = tid; i < 4096; i += 256) {
        w2[i] = W2[i];
        if (SECOND) w1[i] = W1n[i];
    }
    if (tid < 64) sb[tid] = (tid < nmax) ? batch[node0 + tid] : -1;

    // ---- gather phase: 4 threads per node, 16 channels each ----
    {
        int n = tid >> 2;              // 0..63
        int j = tid & 3;               // quad group
        int gn = node0 + n;
        float4 a0, a1, a2, a3;
        if (gn < NN) {
            const float4* yb = (const float4*)y;
            size_t row = (size_t)gn * 16 + j * 4;
            a0 = yb[row + 0]; a1 = yb[row + 1]; a2 = yb[row + 2]; a3 = yb[row + 3];
            const float4* bq = (const float4*)b1 + j * 4;
            float4 q;
            q = bq[0]; a0.x += q.x; a0.y += q.y; a0.z += q.z; a0.w += q.w;
            q = bq[1]; a1.x += q.x; a1.y += q.y; a1.z += q.z; a1.w += q.w;
            q = bq[2]; a2.x += q.x; a2.y += q.y; a2.z += q.z; a2.w += q.w;
            q = bq[3]; a3.x += q.x; a3.y += q.y; a3.z += q.z; a3.w += q.w;
            int beg = g_rowptr[gn], end = g_rowptr[gn + 1];
            if (end > beg) {
                int s = g_esrc[beg];
                for (int e = beg; e + 1 < end; e++) {
                    int s_next = g_esrc[e + 1];
                    const float4* yr = yb + (size_t)s * 16 + j * 4;
                    float4 v;
                    v = yr[0]; a0.x += v.x; a0.y += v.y; a0.z += v.z; a0.w += v.w;
                    v = yr[1]; a1.x += v.x; a1.y += v.y; a1.z += v.z; a1.w += v.w;
                    v = yr[2]; a2.x += v.x; a2.y += v.y; a2.z += v.z; a2.w += v.w;
                    v = yr[3]; a3.x += v.x; a3.y += v.y; a3.z += v.z; a3.w += v.w;
                    s = s_next;
                }
                const float4* yr = yb + (size_t)s * 16 + j * 4;
                float4 v;
                v = yr[0]; a0.x += v.x; a0.y += v.y; a0.z += v.z; a0.w += v.w;
                v = yr[1]; a1.x += v.x; a1.y += v.y; a1.z += v.z; a1.w += v.w;
                v = yr[2]; a2.x += v.x; a2.y += v.y; a2.z += v.z; a2.w += v.w;
                v = yr[3]; a3.x += v.x; a3.y += v.y; a3.z += v.z; a3.w += v.w;
            }
        } else {
            a0 = a1 = a2 = a3 = make_float4(0.f, 0.f, 0.f, 0.f);
        }
        int cb0 = j * 16;
        zs[(cb0 + 0)  * 65 + n] = fmaxf(a0.x, 0.f);
        zs[(cb0 + 1)  * 65 + n] = fmaxf(a0.y, 0.f);
        zs[(cb0 + 2)  * 65 + n] = fmaxf(a0.z, 0.f);
        zs[(cb0 + 3)  * 65 + n] = fmaxf(a0.w, 0.f);
        zs[(cb0 + 4)  * 65 + n] = fmaxf(a1.x, 0.f);
        zs[(cb0 + 5)  * 65 + n] = fmaxf(a1.y, 0.f);
        zs[(cb0 + 6)  * 65 + n] = fmaxf(a1.z, 0.f);
        zs[(cb0 + 7)  * 65 + n] = fmaxf(a1.w, 0.f);
        zs[(cb0 + 8)  * 65 + n] = fmaxf(a2.x, 0.f);
        zs[(cb0 + 9)  * 65 + n] = fmaxf(a2.y, 0.f);
        zs[(cb0 + 10) * 65 + n] = fmaxf(a2.z, 0.f);
        zs[(cb0 + 11) * 65 + n] = fmaxf(a2.w, 0.f);
        zs[(cb0 + 12) * 65 + n] = fmaxf(a3.x, 0.f);
        zs[(cb0 + 13) * 65 + n] = fmaxf(a3.y, 0.f);
        zs[(cb0 + 14) * 65 + n] = fmaxf(a3.z, 0.f);
        zs[(cb0 + 15) * 65 + n] = fmaxf(a3.w, 0.f);
    }
    __syncthreads();

    int n = tid & 63, grp = tid >> 6, cb = grp * 16;
    int gn = node0 + n;

    // ---- GEMM 1: h = relu(z @ W2 + b2) ----
    u64 acc[8];
#pragma unroll
    for (int j = 0; j < 8; j++) acc[j] = pack2(b2[cb + 2 * j], b2[cb + 2 * j + 1]);
    for (int k = 0; k < 64; k++) {
        u64 zz = dup2(zs[k * 65 + n]);
        const ulonglong2* wr = (const ulonglong2*)&w2[k * 64 + cb];
#pragma unroll
        for (int j = 0; j < 4; j++) {
            ulonglong2 w = wr[j];
            fma2(acc[2 * j], zz, w.x);
            fma2(acc[2 * j + 1], zz, w.y);
        }
    }
#pragma unroll
    for (int j = 0; j < 8; j++) {
        float2 a = unpack2(acc[j]);
        hs[(cb + 2 * j) * 65 + n]     = fmaxf(a.x, 0.f);
        hs[(cb + 2 * j + 1) * 65 + n] = fmaxf(a.y, 0.f);
    }
    __syncthreads();

    // ---- pooling: per-graph partial sums of h into pcat (batch is sorted) ----
    {
        int c = tid & 63;          // channel
        int q = tid >> 6;          // node chunk
        int i0 = q * 16;
        if (i0 < nmax) {
            int iend = min(i0 + 16, nmax);
            int cur = sb[i0];
            float s = 0.f;
            for (int i = i0; i < iend; i++) {
                int b = sb[i];
                if (b != cur) {
                    red_f32(&g_pcat[cur * 256 + layer * 64 + c], s);
                    s = 0.f;
                    cur = b;
                }
                s += hs[c * 65 + i];
            }
            red_f32(&g_pcat[cur * 256 + layer * 64 + c], s);
        }
    }

    // ---- GEMM 2: yout = h @ W1_next (yout is the OTHER buffer; no race) ----
    if (!SECOND) return;
    u64 a2[8];
#pragma unroll
    for (int j = 0; j < 8; j++) a2[j] = 0ull;
    for (int k = 0; k < 64; k++) {
        u64 zz = dup2(hs[k * 65 + n]);
        const ulonglong2* wr = (const ulonglong2*)&w1[k * 64 + cb];
#pragma unroll
        for (int j = 0; j < 4; j++) {
            ulonglong2 w = wr[j];
            fma2(a2[2 * j], zz, w.x);
            fma2(a2[2 * j + 1], zz, w.y);
        }
    }
    if (gn < NN) {
        float4* o = (float4*)(yout + (size_t)gn * 64 + cb);
#pragma unroll
        for (int j = 0; j < 4; j++) {
            float2 a = unpack2(a2[2 * j]);
            float2 b = unpack2(a2[2 * j + 1]);
            o[j] = make_float4(a.x, a.y, b.x, b.y);
        }
    }
}

// ---------------- JK projection on pooled ----------------
__global__ void __launch_bounds__(64) proj_kernel(
    const float* __restrict__ Wjk, const float* __restrict__ bjk)
{
    __shared__ float ps[256];
    int g = blockIdx.x, c = threadIdx.x;
    for (int i = c; i < 256; i += 64) ps[i] = g_pcat[g * 256 + i];
    __syncthreads();
    float acc = (float)g_cnt[g] * bjk[c];
    for (int k = 0; k < 256; k++) acc += ps[k] * Wjk[k * 64 + c];
    g_pooled[g * 64 + c] = acc;
}

// ---------------- classifier ----------------
__global__ void __launch_bounds__(128) classifier_kernel(
    const float* __restrict__ Wc1, const float* __restrict__ bc1,
    const float* __restrict__ gamma, const float* __restrict__ beta,
    const float* __restrict__ Wc2, const float* __restrict__ bc2,
    float* __restrict__ out)
{
    extern __shared__ float sm[];
    float* W1s = sm;                  // [64][64]
    float* zsm = W1s + 64 * 64;       // [64][129]
    float* scale_s = zsm + 64 * 129;
    float* shift_s = scale_s + 64;

    int tid = threadIdx.x;
    for (int i = tid; i < 64 * 64; i += 128) W1s[i] = Wc1[i];
    __syncthreads();

    float acc[64];
#pragma unroll
    for (int c = 0; c < 64; c++) acc[c] = bc1[c];
    for (int k = 0; k < 64; k++) {
        float pk = g_pooled[tid * 64 + k];
#pragma unroll
        for (int c = 0; c < 64; c++) acc[c] += pk * W1s[k * 64 + c];
    }
#pragma unroll
    for (int c = 0; c < 64; c++) zsm[c * 129 + tid] = acc[c];
    __syncthreads();

    if (tid < 64) {
        int c = tid;
        float s = 0.f;
        for (int g = 0; g < GNUM; g++) s += zsm[c * 129 + g];
        float mu = s / GNUM;
        float v = 0.f;
        for (int g = 0; g < GNUM; g++) {
            float d = zsm[c * 129 + g] - mu;
            v += d * d;
        }
        v /= GNUM;
        float sc = gamma[c] * rsqrtf(v + 1e-5f);
        scale_s[c] = sc;
        shift_s[c] = beta[c] - mu * sc;
    }
    __syncthreads();

    float o[OUT_CH];
#pragma unroll
    for (int j = 0; j < OUT_CH; j++) o[j] = bc2[j];
    for (int c = 0; c < 64; c++) {
        float zn = fmaxf(zsm[c * 129 + tid] * scale_s[c] + shift_s[c], 0.f);
#pragma unroll
        for (int j = 0; j < OUT_CH; j++) o[j] += zn * Wc2[c * OUT_CH + j];
    }
#pragma unroll
    for (int j = 0; j < OUT_CH; j++) out[tid * OUT_CH + j] = o[j];
}

// ---------------- launch ----------------
extern "C" void kernel_launch(void* const* d_in, const int* in_sizes, int n_in,
                              void* d_out, int out_size)
{
    const float* x     = (const float*)d_in[0];
    const int*   ei    = (const int*)d_in[1];
    const int*   batch = (const int*)d_in[2];
    const float* W1f = (const float*)d_in[3];
    const float* b1f = (const float*)d_in[4];
    const float* W2f = (const float*)d_in[5];
    const float* b2f = (const float*)d_in[6];
    const float* W1r = (const float*)d_in[7];
    const float* b1r = (const float*)d_in[8];
    const float* W2r = (const float*)d_in[9];
    const float* b2r = (const float*)d_in[10];
    const float* Wjk = (const float*)d_in[11];
    const float* bjk = (const float*)d_in[12];
    const float* Wc1 = (const float*)d_in[13];
    const float* bc1 = (const float*)d_in[14];
    const float* gm  = (const float*)d_in[15];
    const float* bt  = (const float*)d_in[16];
    const float* Wc2 = (const float*)d_in[17];
    const float* bc2 = (const float*)d_in[18];
    float* out = (float*)d_out;

    void *p_deg, *p_pcat, *p_cnt, *p_y, *p_y2;
    cudaGetSymbolAddress(&p_deg, g_deg);
    cudaGetSymbolAddress(&p_pcat, g_pcat);
    cudaGetSymbolAddress(&p_cnt, g_cnt);
    cudaGetSymbolAddress(&p_y, g_y);
    cudaGetSymbolAddress(&p_y2, g_y2);
    float* ybuf[2] = { (float*)p_y, (float*)p_y2 };

    const size_t SM_Y0  = (128 * 65 + 128 * 64) * sizeof(float);                 // 66048
    const size_t SM_MLP = (64 * 65 * 2 + 4096 * 2) * sizeof(float) + 64 * 4;     // 66304
    const size_t SM_CLS = (64 * 64 + 64 * 129 + 128) * sizeof(float);            // 49920

    cudaFuncSetAttribute(gemm_y0_kernel, cudaFuncAttributeMaxDynamicSharedMemorySize, (int)SM_Y0);
    cudaFuncSetAttribute(layer_kernel<true>,  cudaFuncAttributeMaxDynamicSharedMemorySize, (int)SM_MLP);
    cudaFuncSetAttribute(layer_kernel<false>, cudaFuncAttributeMaxDynamicSharedMemorySize, (int)SM_MLP);
    cudaFuncSetAttribute(classifier_kernel, cudaFuncAttributeMaxDynamicSharedMemorySize, (int)SM_CLS);

    const int EB = (NE + 255) / 256;       // 6250
    const int SB = (NN + 1023) / 1024;     // 98
    const int GB64 = (NN + 63) / 64;       // 1563

    // fork a side stream for the CSR build (capture-legal event fork/join)
    cudaStream_t s1;
    cudaStreamCreateWithFlags(&s1, cudaStreamNonBlocking);
    cudaEvent_t evFork, evJoin;
    cudaEventCreateWithFlags(&evFork, cudaEventDisableTiming);
    cudaEventCreateWithFlags(&evJoin, cudaEventDisableTiming);

    cudaEventRecord(evFork, 0);
    cudaStreamWaitEvent(s1, evFork, 0);

    // --- side stream: CSR build + graph counts ---
    cudaMemsetAsync(p_deg, 0, NN * sizeof(int), s1);
    cudaMemsetAsync(p_cnt, 0, GNUM * sizeof(int), s1);
    hist_kernel<<<EB, 256, 0, s1>>>(ei);
    scan1_kernel<<<SB, 256, 0, s1>>>();
    scan2_kernel<<<1, 128, 0, s1>>>(SB);
    scan3_kernel<<<SB, 256, 0, s1>>>();
    fill_kernel<<<EB, 256, 0, s1>>>(ei);
    cnt_kernel<<<(NN + 255) / 256, 256, 0, s1>>>(batch);
    cudaEventRecord(evJoin, s1);

    // --- main stream: pcat zero + y0 = x @ W1f (overlaps CSR build) ---
    cudaMemsetAsync(p_pcat, 0, GNUM * 256 * sizeof(float), 0);
    gemm_y0_kernel<<<GB64, 256, SM_Y0>>>(x, W1f);

    // join
    cudaStreamWaitEvent(0, evJoin, 0);

    // --- fused layers (ping-pong y buffers to avoid read/write race) ---
    for (int l = 0; l < 4; l++) {
        const float* b1 = (l == 0) ? b1f : b1r + (size_t)(l - 1) * 64;
        const float* W2 = (l == 0) ? W2f : W2r + (size_t)(l - 1) * 4096;
        const float* b2 = (l == 0) ? b2f : b2r + (size_t)(l - 1) * 64;
        const float* yin = ybuf[l & 1];
        float* yo = ybuf[(l + 1) & 1];
        if (l < 3) {
            const float* W1n = W1r + (size_t)l * 4096;
            layer_kernel<true><<<GB64, 256, SM_MLP>>>(yin, b1, W2, b2, batch, l, W1n, yo);
        } else {
            layer_kernel<false><<<GB64, 256, SM_MLP>>>(yin, b1, W2, b2, batch, l, nullptr, nullptr);
        }
    }

    // --- JK projection + classifier ---
    proj_kernel<<<GNUM, 64>>>(Wjk, bjk);
    classifier_kernel<<<1, 128, SM_CLS>>>(Wc1, bc1, gm, bt, Wc2, bc2, out);
}

// round 12
// speedup vs baseline: 1.2001x; 1.2001x over previous
#include <cuda_runtime.h>
#include <cstdint>

#define NN 100000
#define NE 1600000
#define GNUM 128
#define OUT_CH 10

typedef unsigned long long u64;

// ---------------- device scratch ----------------
__device__ int   g_deg[NN];
__device__ int   g_rowptr[NN + 1];
__device__ int   g_cursor[NN];
__device__ int   g_esrc[NE];
__device__ int   g_bsum[128];
__device__ float g_y[(size_t)NN * 64];
__device__ float g_t[(size_t)NN * 64];
__device__ float g_pcat[GNUM * 256];            // k = layer*64 + c
__device__ int   g_cnt[GNUM];
__device__ float g_pooled[GNUM * 64];

// ---------------- f32x2 helpers ----------------
__device__ __forceinline__ u64 pack2(float lo, float hi) {
    u64 r; asm("mov.b64 %0, {%1, %2};" : "=l"(r) : "f"(lo), "f"(hi)); return r;
}
__device__ __forceinline__ u64 dup2(float v) {
    u64 r; asm("mov.b64 %0, {%1, %1};" : "=l"(r) : "f"(v)); return r;
}
__device__ __forceinline__ void fma2(u64& d, u64 a, u64 b) {
    asm("fma.rn.f32x2 %0, %1, %2, %0;" : "+l"(d) : "l"(a), "l"(b));
}
__device__ __forceinline__ float2 unpack2(u64 v) {
    float2 f; asm("mov.b64 {%0, %1}, %2;" : "=f"(f.x), "=f"(f.y) : "l"(v)); return f;
}
__device__ __forceinline__ void red_f32(float* p, float v) {
    asm volatile("red.global.add.f32 [%0], %1;" :: "l"(p), "f"(v) : "memory");
}

// ---------------- CSR build ----------------
__global__ void hist_kernel(const int* __restrict__ ei) {
    int e = blockIdx.x * blockDim.x + threadIdx.x;
    if (e < NE) atomicAdd(&g_deg[ei[NE + e]], 1);
}

__global__ void scan1_kernel() {
    __shared__ int wsum[8];
    int tid = threadIdx.x;
    int base = blockIdx.x * 1024 + tid * 4;
    int v[4];
#pragma unroll
    for (int i = 0; i < 4; i++) v[i] = (base + i < NN) ? g_deg[base + i] : 0;
    int s = v[0] + v[1] + v[2] + v[3];
    int lane = tid & 31, w = tid >> 5;
    int inc = s;
    for (int o = 1; o < 32; o <<= 1) {
        int t = __shfl_up_sync(0xffffffffu, inc, o);
        if (lane >= o) inc += t;
    }
    if (lane == 31) wsum[w] = inc;
    __syncthreads();
    if (tid < 8) {
        int x = wsum[tid];
        int inc2 = x;
        for (int o = 1; o < 8; o <<= 1) {
            int t = __shfl_up_sync(0xffu, inc2, o);
            if (tid >= o) inc2 += t;
        }
        wsum[tid] = inc2 - x;
        if (tid == 7) g_bsum[blockIdx.x] = inc2;
    }
    __syncthreads();
    int run = wsum[w] + inc - s;
#pragma unroll
    for (int i = 0; i < 4; i++) {
        if (base + i < NN) g_deg[base + i] = run;
        run += v[i];
    }
}

__global__ void scan2_kernel(int nb) {
    __shared__ int ws[4];
    int tid = threadIdx.x;
    int v = (tid < nb) ? g_bsum[tid] : 0;
    int lane = tid & 31, w = tid >> 5;
    int inc = v;
    for (int o = 1; o < 32; o <<= 1) {
        int t = __shfl_up_sync(0xffffffffu, inc, o);
        if (lane >= o) inc += t;
    }
    if (lane == 31) ws[w] = inc;
    __syncthreads();
    int add = 0;
    for (int i = 0; i < w; i++) add += ws[i];
    if (tid < nb) g_bsum[tid] = add + inc - v;
}

__global__ void scan3_kernel() {
    int tid = threadIdx.x;
    int base = blockIdx.x * 1024 + tid * 4;
    int add = g_bsum[blockIdx.x];
#pragma unroll
    for (int i = 0; i < 4; i++) {
        int idx = base + i;
        if (idx < NN) {
            int r = g_deg[idx] + add;
            g_rowptr[idx] = r;
            g_cursor[idx] = r;
        }
    }
    if (blockIdx.x == 0 && tid == 0) g_rowptr[NN] = NE;
}

__global__ void fill_kernel(const int* __restrict__ ei) {
    int e = blockIdx.x * blockDim.x + threadIdx.x;
    if (e < NE) {
        int d = ei[NE + e];
        int p = atomicAdd(&g_cursor[d], 1);
        g_esrc[p] = ei[e];
    }
}

// ---------------- graph counts ----------------
__global__ void cnt_kernel(const int* __restrict__ batch) {
    __shared__ int h[GNUM];
    int tid = threadIdx.x;
    if (tid < GNUM) h[tid] = 0;
    __syncthreads();
    int i = blockIdx.x * 256 + tid;
    if (i < NN) atomicAdd(&h[batch[i]], 1);
    __syncthreads();
    if (tid < GNUM && h[tid]) atomicAdd(&g_cnt[tid], h[tid]);
}

// ---------------- y0 = x @ W1f (K=128 -> 64), f32x2 ----------------
__global__ void __launch_bounds__(256) gemm_y0_kernel(
    const float* __restrict__ x, const float* __restrict__ W)
{
    extern __shared__ float sm[];
    float* zs = sm;            // [128][65]
    float* ws = zs + 128 * 65; // [128][64]
    int tid = threadIdx.x;
    int node0 = blockIdx.x * 64;

    for (int i = tid; i < 128 * 64; i += 256) ws[i] = W[i];
    for (int i = tid; i < 2048; i += 256) {     // 64 nodes x 32 float4
        int n = i >> 5, kq = i & 31;
        int gn = node0 + n;
        float4 v = (gn < NN) ? *(const float4*)(x + (size_t)gn * 128 + kq * 4)
                             : make_float4(0.f, 0.f, 0.f, 0.f);
        zs[(4 * kq + 0) * 65 + n] = v.x;
        zs[(4 * kq + 1) * 65 + n] = v.y;
        zs[(4 * kq + 2) * 65 + n] = v.z;
        zs[(4 * kq + 3) * 65 + n] = v.w;
    }
    __syncthreads();

    int n = tid & 63, grp = tid >> 6, cb = grp * 16;
    u64 acc[8];
#pragma unroll
    for (int j = 0; j < 8; j++) acc[j] = 0ull;
    for (int k = 0; k < 128; k++) {
        u64 zz = dup2(zs[k * 65 + n]);
        const ulonglong2* wr = (const ulonglong2*)&ws[k * 64 + cb];
#pragma unroll
        for (int j = 0; j < 4; j++) {
            ulonglong2 w = wr[j];
            fma2(acc[2 * j], zz, w.x);
            fma2(acc[2 * j + 1], zz, w.y);
        }
    }
    int gn = node0 + n;
    if (gn < NN) {
        float4* o = (float4*)(g_y + (size_t)gn * 64 + cb);
#pragma unroll
        for (int j = 0; j < 4; j++) {
            float2 a = unpack2(acc[2 * j]);
            float2 b = unpack2(acc[2 * j + 1]);
            o[j] = make_float4(a.x, a.y, b.x, b.y);
        }
    }
}

// ---------------- gather: t[n] = relu(y[n] + sum_in y[src] + b1) ----------------
// 16 threads per node, 2-way edge unroll with independent accumulators for MLP.
__global__ void __launch_bounds__(256) gather_kernel(
    const float* __restrict__ y, const float* __restrict__ b1,
    float* __restrict__ tout)
{
    int tid = threadIdx.x;
    int n = blockIdx.x * 16 + (tid >> 4);
    int q = tid & 15;
    if (n >= NN) return;
    int beg = g_rowptr[n], end = g_rowptr[n + 1];
    const float4* yb = (const float4*)y;
    float4 a = yb[(size_t)n * 16 + q];
    float4 bb = *(const float4*)(b1 + q * 4);
    a.x += bb.x; a.y += bb.y; a.z += bb.z; a.w += bb.w;
    float4 a2 = make_float4(0.f, 0.f, 0.f, 0.f);
    int e = beg;
    for (; e + 1 < end; e += 2) {
        int s0 = g_esrc[e];
        int s1 = g_esrc[e + 1];
        float4 v0 = yb[(size_t)s0 * 16 + q];
        float4 v1 = yb[(size_t)s1 * 16 + q];
        a.x  += v0.x; a.y  += v0.y; a.z  += v0.z; a.w  += v0.w;
        a2.x += v1.x; a2.y += v1.y; a2.z += v1.z; a2.w += v1.w;
    }
    if (e < end) {
        int s0 = g_esrc[e];
        float4 v0 = yb[(size_t)s0 * 16 + q];
        a.x += v0.x; a.y += v0.y; a.z += v0.z; a.w += v0.w;
    }
    a.x += a2.x; a.y += a2.y; a.z += a2.z; a.w += a2.w;
    *(float4*)(tout + (size_t)n * 64 + q * 4) =
        make_float4(fmaxf(a.x, 0.f), fmaxf(a.y, 0.f), fmaxf(a.z, 0.f), fmaxf(a.w, 0.f));
}

// -------- fused: h = relu(t@W2+b2); pool h per-graph into pcat; y = h@W1n (if SECOND) --------
template<bool SECOND>
__global__ void __launch_bounds__(256) mlp2_kernel(
    const float* __restrict__ tin,
    const float* __restrict__ W2, const float* __restrict__ b2,
    const int* __restrict__ batch, int layer,
    const float* __restrict__ W1n, float* __restrict__ yout)
{
    extern __shared__ float sm[];
    float* zs = sm;              // [64][65]
    float* w2 = zs + 64 * 65;    // [64][64]
    float* hs = w2 + 4096;       // [64][65]  (h transposed [c][n])
    float* w1 = hs + 64 * 65;    // [64][64]
    int*   sb = (int*)(w1 + 4096); // [64] batch ids
    int tid = threadIdx.x;
    int node0 = blockIdx.x * 64;
    int nmax = min(64, NN - node0);

    for (int i = tid; i < 4096; i += 256) {
        w2[i] = W2[i];
        if (SECOND) w1[i] = W1n[i];
    }
    if (tid < 64) sb[tid] = (tid < nmax) ? batch[node0 + tid] : -1;
    for (int i = tid; i < 1024; i += 256) {    // 64 nodes x 16 float4
        int n = i >> 4, kq = i & 15;
        int gn = node0 + n;
        float4 v = (gn < NN) ? *(const float4*)(tin + (size_t)gn * 64 + kq * 4)
                             : make_float4(0.f, 0.f, 0.f, 0.f);
        zs[(4 * kq + 0) * 65 + n] = v.x;
        zs[(4 * kq + 1) * 65 + n] = v.y;
        zs[(4 * kq + 2) * 65 + n] = v.z;
        zs[(4 * kq + 3) * 65 + n] = v.w;
    }
    __syncthreads();

    int n = tid & 63, grp = tid >> 6, cb = grp * 16;
    int gn = node0 + n;

    // ---- GEMM 1: h = relu(t @ W2 + b2) ----
    u64 acc[8];
#pragma unroll
    for (int j = 0; j < 8; j++) acc[j] = pack2(b2[cb + 2 * j], b2[cb + 2 * j + 1]);
    for (int k = 0; k < 64; k++) {
        u64 zz = dup2(zs[k * 65 + n]);
        const ulonglong2* wr = (const ulonglong2*)&w2[k * 64 + cb];
#pragma unroll
        for (int j = 0; j < 4; j++) {
            ulonglong2 w = wr[j];
            fma2(acc[2 * j], zz, w.x);
            fma2(acc[2 * j + 1], zz, w.y);
        }
    }
#pragma unroll
    for (int j = 0; j < 8; j++) {
        float2 a = unpack2(acc[j]);
        hs[(cb + 2 * j) * 65 + n]     = fmaxf(a.x, 0.f);
        hs[(cb + 2 * j + 1) * 65 + n] = fmaxf(a.y, 0.f);
    }
    __syncthreads();

    // ---- pooling: per-graph partial sums of h into pcat (batch is sorted) ----
    {
        int c = tid & 63;          // channel
        int q = tid >> 6;          // node chunk
        int i0 = q * 16;
        if (i0 < nmax) {
            int iend = min(i0 + 16, nmax);
            int cur = sb[i0];
            float s = 0.f;
            for (int i = i0; i < iend; i++) {
                int b = sb[i];
                if (b != cur) {
                    red_f32(&g_pcat[cur * 256 + layer * 64 + c], s);
                    s = 0.f;
                    cur = b;
                }
                s += hs[c * 65 + i];
            }
            red_f32(&g_pcat[cur * 256 + layer * 64 + c], s);
        }
    }

    // ---- GEMM 2: y = h @ W1_next ----
    if (!SECOND) return;
    u64 a2[8];
#pragma unroll
    for (int j = 0; j < 8; j++) a2[j] = 0ull;
    for (int k = 0; k < 64; k++) {
        u64 zz = dup2(hs[k * 65 + n]);
        const ulonglong2* wr = (const ulonglong2*)&w1[k * 64 + cb];
#pragma unroll
        for (int j = 0; j < 4; j++) {
            ulonglong2 w = wr[j];
            fma2(a2[2 * j], zz, w.x);
            fma2(a2[2 * j + 1], zz, w.y);
        }
    }
    if (gn < NN) {
        float4* o = (float4*)(yout + (size_t)gn * 64 + cb);
#pragma unroll
        for (int j = 0; j < 4; j++) {
            float2 a = unpack2(a2[2 * j]);
            float2 b = unpack2(a2[2 * j + 1]);
            o[j] = make_float4(a.x, a.y, b.x, b.y);
        }
    }
}

// ---------------- JK projection on pooled ----------------
__global__ void __launch_bounds__(64) proj_kernel(
    const float* __restrict__ Wjk, const float* __restrict__ bjk)
{
    __shared__ float ps[256];
    int g = blockIdx.x, c = threadIdx.x;
    for (int i = c; i < 256; i += 64) ps[i] = g_pcat[g * 256 + i];
    __syncthreads();
    float acc = (float)g_cnt[g] * bjk[c];
    for (int k = 0; k < 256; k++) acc += ps[k] * Wjk[k * 64 + c];
    g_pooled[g * 64 + c] = acc;
}

// ---------------- classifier ----------------
__global__ void __launch_bounds__(128) classifier_kernel(
    const float* __restrict__ Wc1, const float* __restrict__ bc1,
    const float* __restrict__ gamma, const float* __restrict__ beta,
    const float* __restrict__ Wc2, const float* __restrict__ bc2,
    float* __restrict__ out)
{
    extern __shared__ float sm[];
    float* W1s = sm;                  // [64][64]
    float* zsm = W1s + 64 * 64;       // [64][129]
    float* scale_s = zsm + 64 * 129;
    float* shift_s = scale_s + 64;

    int tid = threadIdx.x;
    for (int i = tid; i < 64 * 64; i += 128) W1s[i] = Wc1[i];
    __syncthreads();

    float acc[64];
#pragma unroll
    for (int c = 0; c < 64; c++) acc[c] = bc1[c];
    for (int k = 0; k < 64; k++) {
        float pk = g_pooled[tid * 64 + k];
#pragma unroll
        for (int c = 0; c < 64; c++) acc[c] += pk * W1s[k * 64 + c];
    }
#pragma unroll
    for (int c = 0; c < 64; c++) zsm[c * 129 + tid] = acc[c];
    __syncthreads();

    if (tid < 64) {
        int c = tid;
        float s = 0.f;
        for (int g = 0; g < GNUM; g++) s += zsm[c * 129 + g];
        float mu = s / GNUM;
        float v = 0.f;
        for (int g = 0; g < GNUM; g++) {
            float d = zsm[c * 129 + g] - mu;
            v += d * d;
        }
        v /= GNUM;
        float sc = gamma[c] * rsqrtf(v + 1e-5f);
        scale_s[c] = sc;
        shift_s[c] = beta[c] - mu * sc;
    }
    __syncthreads();

    float o[OUT_CH];
#pragma unroll
    for (int j = 0; j < OUT_CH; j++) o[j] = bc2[j];
    for (int c = 0; c < 64; c++) {
        float zn = fmaxf(zsm[c * 129 + tid] * scale_s[c] + shift_s[c], 0.f);
#pragma unroll
        for (int j = 0; j < OUT_CH; j++) o[j] += zn * Wc2[c * OUT_CH + j];
    }
#pragma unroll
    for (int j = 0; j < OUT_CH; j++) out[tid * OUT_CH + j] = o[j];
}

// ---------------- launch ----------------
extern "C" void kernel_launch(void* const* d_in, const int* in_sizes, int n_in,
                              void* d_out, int out_size)
{
    const float* x     = (const float*)d_in[0];
    const int*   ei    = (const int*)d_in[1];
    const int*   batch = (const int*)d_in[2];
    const float* W1f = (const float*)d_in[3];
    const float* b1f = (const float*)d_in[4];
    const float* W2f = (const float*)d_in[5];
    const float* b2f = (const float*)d_in[6];
    const float* W1r = (const float*)d_in[7];
    const float* b1r = (const float*)d_in[8];
    const float* W2r = (const float*)d_in[9];
    const float* b2r = (const float*)d_in[10];
    const float* Wjk = (const float*)d_in[11];
    const float* bjk = (const float*)d_in[12];
    const float* Wc1 = (const float*)d_in[13];
    const float* bc1 = (const float*)d_in[14];
    const float* gm  = (const float*)d_in[15];
    const float* bt  = (const float*)d_in[16];
    const float* Wc2 = (const float*)d_in[17];
    const float* bc2 = (const float*)d_in[18];
    float* out = (float*)d_out;

    void *p_deg, *p_pcat, *p_cnt, *p_y;
    cudaGetSymbolAddress(&p_deg, g_deg);
    cudaGetSymbolAddress(&p_pcat, g_pcat);
    cudaGetSymbolAddress(&p_cnt, g_cnt);
    cudaGetSymbolAddress(&p_y, g_y);
    float* y = (float*)p_y;
    void* p_t;
    cudaGetSymbolAddress(&p_t, g_t);
    float* t = (float*)p_t;

    const size_t SM_Y0  = (128 * 65 + 128 * 64) * sizeof(float);                 // 66048
    const size_t SM_MLP = (64 * 65 * 2 + 4096 * 2) * sizeof(float) + 64 * 4;     // 66304
    const size_t SM_CLS = (64 * 64 + 64 * 129 + 128) * sizeof(float);            // 49920

    cudaFuncSetAttribute(gemm_y0_kernel, cudaFuncAttributeMaxDynamicSharedMemorySize, (int)SM_Y0);
    cudaFuncSetAttribute(mlp2_kernel<true>,  cudaFuncAttributeMaxDynamicSharedMemorySize, (int)SM_MLP);
    cudaFuncSetAttribute(mlp2_kernel<false>, cudaFuncAttributeMaxDynamicSharedMemorySize, (int)SM_MLP);
    cudaFuncSetAttribute(classifier_kernel, cudaFuncAttributeMaxDynamicSharedMemorySize, (int)SM_CLS);

    const int EB = (NE + 255) / 256;       // 6250
    const int SB = (NN + 1023) / 1024;     // 98
    const int GB64 = (NN + 63) / 64;       // 1563
    const int GB16 = (NN + 15) / 16;       // 6250

    // fork a side stream for the CSR build (capture-legal event fork/join)
    cudaStream_t s1;
    cudaStreamCreateWithFlags(&s1, cudaStreamNonBlocking);
    cudaEvent_t evFork, evJoin;
    cudaEventCreateWithFlags(&evFork, cudaEventDisableTiming);
    cudaEventCreateWithFlags(&evJoin, cudaEventDisableTiming);

    cudaEventRecord(evFork, 0);
    cudaStreamWaitEvent(s1, evFork, 0);

    // --- side stream: CSR build + graph counts ---
    cudaMemsetAsync(p_deg, 0, NN * sizeof(int), s1);
    cudaMemsetAsync(p_cnt, 0, GNUM * sizeof(int), s1);
    hist_kernel<<<EB, 256, 0, s1>>>(ei);
    scan1_kernel<<<SB, 256, 0, s1>>>();
    scan2_kernel<<<1, 128, 0, s1>>>(SB);
    scan3_kernel<<<SB, 256, 0, s1>>>();
    fill_kernel<<<EB, 256, 0, s1>>>(ei);
    cnt_kernel<<<(NN + 255) / 256, 256, 0, s1>>>(batch);
    cudaEventRecord(evJoin, s1);

    // --- main stream: pcat zero + y0 = x @ W1f (overlaps CSR build) ---
    cudaMemsetAsync(p_pcat, 0, GNUM * 256 * sizeof(float), 0);
    gemm_y0_kernel<<<GB64, 256, SM_Y0>>>(x, W1f);

    // join
    cudaStreamWaitEvent(0, evJoin, 0);

    // --- layers: gather (y -> t), then fused MLP+pool (t -> y) ---
    for (int l = 0; l < 4; l++) {
        const float* b1 = (l == 0) ? b1f : b1r + (size_t)(l - 1) * 64;
        const float* W2 = (l == 0) ? W2f : W2r + (size_t)(l - 1) * 4096;
        const float* b2 = (l == 0) ? b2f : b2r + (size_t)(l - 1) * 64;
        gather_kernel<<<GB16, 256>>>(y, b1, t);
        if (l < 3) {
            const float* W1n = W1r + (size_t)l * 4096;
            mlp2_kernel<true><<<GB64, 256, SM_MLP>>>(t, W2, b2, batch, l, W1n, y);
        } else {
            mlp2_kernel<false><<<GB64, 256, SM_MLP>>>(t, W2, b2, batch, l, nullptr, nullptr);
        }
    }

    // --- JK projection + classifier ---
    proj_kernel<<<GNUM, 64>>>(Wjk, bjk);
    classifier_kernel<<<1, 128, SM_CLS>>>(Wc1, bc1, gm, bt, Wc2, bc2, out);
}

// round 15
// speedup vs baseline: 1.2707x; 1.0589x over previous
#include <cuda_runtime.h>
#include <cuda_fp16.h>
#include <cstdint>

#define NN 100000
#define NE 1600000
#define GNUM 128
#define OUT_CH 10

typedef unsigned long long u64;

// ---------------- device scratch ----------------
__device__ int    g_deg[NN];
__device__ int    g_rowptr[NN + 1];
__device__ int    g_cursor[NN];
__device__ int    g_esrc[NE];
__device__ int    g_bsum[128];
__device__ __half g_y[(size_t)NN * 64];          // fp16 message table (128 B/row)
__device__ float  g_t[(size_t)NN * 64];
__device__ float  g_pcat[GNUM * 256];            // k = layer*64 + c
__device__ int    g_cnt[GNUM];
__device__ float  g_pooled[GNUM * 64];

// ---------------- f32x2 helpers ----------------
__device__ __forceinline__ u64 pack2(float lo, float hi) {
    u64 r; asm("mov.b64 %0, {%1, %2};" : "=l"(r) : "f"(lo), "f"(hi)); return r;
}
__device__ __forceinline__ u64 dup2(float v) {
    u64 r; asm("mov.b64 %0, {%1, %1};" : "=l"(r) : "f"(v)); return r;
}
__device__ __forceinline__ void fma2(u64& d, u64 a, u64 b) {
    asm("fma.rn.f32x2 %0, %1, %2, %0;" : "+l"(d) : "l"(a), "l"(b));
}
__device__ __forceinline__ float2 unpack2(u64 v) {
    float2 f; asm("mov.b64 {%0, %1}, %2;" : "=f"(f.x), "=f"(f.y) : "l"(v)); return f;
}
// pack f32x2-accumulator (u64) straight to packed fp16x2 bits
__device__ __forceinline__ unsigned int f32x2_to_h2(u64 v) {
    float2 f = unpack2(v);
    unsigned int r;
    asm("cvt.rn.f16x2.f32 %0, %1, %2;" : "=r"(r) : "f"(f.y), "f"(f.x));
    return r;
}
__device__ __forceinline__ void red_f32(float* p, float v) {
    asm volatile("red.global.add.f32 [%0], %1;" :: "l"(p), "f"(v) : "memory");
}

// ---------------- CSR build ----------------
__global__ void hist_kernel(const int* __restrict__ ei) {
    int e = blockIdx.x * blockDim.x + threadIdx.x;
    if (e < NE) atomicAdd(&g_deg[ei[NE + e]], 1);
}

__global__ void scan1_kernel() {
    __shared__ int wsum[8];
    int tid = threadIdx.x;
    int base = blockIdx.x * 1024 + tid * 4;
    int v[4];
#pragma unroll
    for (int i = 0; i < 4; i++) v[i] = (base + i < NN) ? g_deg[base + i] : 0;
    int s = v[0] + v[1] + v[2] + v[3];
    int lane = tid & 31, w = tid >> 5;
    int inc = s;
    for (int o = 1; o < 32; o <<= 1) {
        int t = __shfl_up_sync(0xffffffffu, inc, o);
        if (lane >= o) inc += t;
    }
    if (lane == 31) wsum[w] = inc;
    __syncthreads();
    if (tid < 8) {
        int x = wsum[tid];
        int inc2 = x;
        for (int o = 1; o < 8; o <<= 1) {
            int t = __shfl_up_sync(0xffu, inc2, o);
            if (tid >= o) inc2 += t;
        }
        wsum[tid] = inc2 - x;
        if (tid == 7) g_bsum[blockIdx.x] = inc2;
    }
    __syncthreads();
    int run = wsum[w] + inc - s;
#pragma unroll
    for (int i = 0; i < 4; i++) {
        if (base + i < NN) g_deg[base + i] = run;
        run += v[i];
    }
}

__global__ void scan2_kernel(int nb) {
    __shared__ int ws[4];
    int tid = threadIdx.x;
    int v = (tid < nb) ? g_bsum[tid] : 0;
    int lane = tid & 31, w = tid >> 5;
    int inc = v;
    for (int o = 1; o < 32; o <<= 1) {
        int t = __shfl_up_sync(0xffffffffu, inc, o);
        if (lane >= o) inc += t;
    }
    if (lane == 31) ws[w] = inc;
    __syncthreads();
    int add = 0;
    for (int i = 0; i < w; i++) add += ws[i];
    if (tid < nb) g_bsum[tid] = add + inc - v;
}

__global__ void scan3_kernel() {
    int tid = threadIdx.x;
    int base = blockIdx.x * 1024 + tid * 4;
    int add = g_bsum[blockIdx.x];
#pragma unroll
    for (int i = 0; i < 4; i++) {
        int idx = base + i;
        if (idx < NN) {
            int r = g_deg[idx] + add;
            g_rowptr[idx] = r;
            g_cursor[idx] = r;
        }
    }
    if (blockIdx.x == 0 && tid == 0) g_rowptr[NN] = NE;
}

__global__ void fill_kernel(const int* __restrict__ ei) {
    int e = blockIdx.x * blockDim.x + threadIdx.x;
    if (e < NE) {
        int d = ei[NE + e];
        int p = atomicAdd(&g_cursor[d], 1);
        g_esrc[p] = ei[e];
    }
}

// ---------------- graph counts ----------------
__global__ void cnt_kernel(const int* __restrict__ batch) {
    __shared__ int h[GNUM];
    int tid = threadIdx.x;
    if (tid < GNUM) h[tid] = 0;
    __syncthreads();
    int i = blockIdx.x * 256 + tid;
    if (i < NN) atomicAdd(&h[batch[i]], 1);
    __syncthreads();
    if (tid < GNUM && h[tid]) atomicAdd(&g_cnt[tid], h[tid]);
}

// ---------------- y0 = x @ W1f (K=128 -> 64), f32x2, fp16 output ----------------
__global__ void __launch_bounds__(256) gemm_y0_kernel(
    const float* __restrict__ x, const float* __restrict__ W)
{
    extern __shared__ float sm[];
    float* zs = sm;            // [128][65]
    float* ws = zs + 128 * 65; // [128][64]
    int tid = threadIdx.x;
    int node0 = blockIdx.x * 64;

    for (int i = tid; i < 128 * 64; i += 256) ws[i] = W[i];
    for (int i = tid; i < 2048; i += 256) {     // 64 nodes x 32 float4
        int n = i >> 5, kq = i & 31;
        int gn = node0 + n;
        float4 v = (gn < NN) ? *(const float4*)(x + (size_t)gn * 128 + kq * 4)
                             : make_float4(0.f, 0.f, 0.f, 0.f);
        zs[(4 * kq + 0) * 65 + n] = v.x;
        zs[(4 * kq + 1) * 65 + n] = v.y;
        zs[(4 * kq + 2) * 65 + n] = v.z;
        zs[(4 * kq + 3) * 65 + n] = v.w;
    }
    __syncthreads();

    int n = tid & 63, grp = tid >> 6, cb = grp * 16;
    u64 acc[8];
#pragma unroll
    for (int j = 0; j < 8; j++) acc[j] = 0ull;
    for (int k = 0; k < 128; k++) {
        u64 zz = dup2(zs[k * 65 + n]);
        const ulonglong2* wr = (const ulonglong2*)&ws[k * 64 + cb];
#pragma unroll
        for (int j = 0; j < 4; j++) {
            ulonglong2 w = wr[j];
            fma2(acc[2 * j], zz, w.x);
            fma2(acc[2 * j + 1], zz, w.y);
        }
    }
    int gn = node0 + n;
    if (gn < NN) {
        uint4 o0, o1;
        o0.x = f32x2_to_h2(acc[0]);
        o0.y = f32x2_to_h2(acc[1]);
        o0.z = f32x2_to_h2(acc[2]);
        o0.w = f32x2_to_h2(acc[3]);
        o1.x = f32x2_to_h2(acc[4]);
        o1.y = f32x2_to_h2(acc[5]);
        o1.z = f32x2_to_h2(acc[6]);
        o1.w = f32x2_to_h2(acc[7]);
        uint4* o = (uint4*)(g_y + (size_t)gn * 64 + cb);
        o[0] = o0;
        o[1] = o1;
    }
}

// ---------------- gather: t[n] = relu(y[n] + sum_in y[src] + b1), y in fp16 ----------------
// 16 threads per node, each handles 4 channels (8 B loads); 2-way edge unroll.
__global__ void __launch_bounds__(256) gather_kernel(
    const __half* __restrict__ y, const float* __restrict__ b1,
    float* __restrict__ tout)
{
    int tid = threadIdx.x;
    int n = blockIdx.x * 16 + (tid >> 4);
    int q = tid & 15;
    if (n >= NN) return;
    int beg = g_rowptr[n], end = g_rowptr[n + 1];
    const uint2* yb = (const uint2*)y;     // 4 halves per uint2; row = 16 uint2

    uint2 v = yb[(size_t)n * 16 + q];
    float2 f0 = __half22float2(*(const __half2*)&v.x);
    float2 f1 = __half22float2(*(const __half2*)&v.y);
    float4 bb = *(const float4*)(b1 + q * 4);
    float4 a  = make_float4(f0.x + bb.x, f0.y + bb.y, f1.x + bb.z, f1.y + bb.w);
    float4 a2 = make_float4(0.f, 0.f, 0.f, 0.f);

    int e = beg;
    for (; e + 1 < end; e += 2) {
        int s0 = g_esrc[e];
        int s1 = g_esrc[e + 1];
        uint2 v0 = yb[(size_t)s0 * 16 + q];
        uint2 v1 = yb[(size_t)s1 * 16 + q];
        float2 g0 = __half22float2(*(const __half2*)&v0.x);
        float2 g1 = __half22float2(*(const __half2*)&v0.y);
        float2 h0 = __half22float2(*(const __half2*)&v1.x);
        float2 h1 = __half22float2(*(const __half2*)&v1.y);
        a.x  += g0.x; a.y  += g0.y; a.z  += g1.x; a.w  += g1.y;
        a2.x += h0.x; a2.y += h0.y; a2.z += h1.x; a2.w += h1.y;
    }
    if (e < end) {
        int s0 = g_esrc[e];
        uint2 v0 = yb[(size_t)s0 * 16 + q];
        float2 g0 = __half22float2(*(const __half2*)&v0.x);
        float2 g1 = __half22float2(*(const __half2*)&v0.y);
        a.x += g0.x; a.y += g0.y; a.z += g1.x; a.w += g1.y;
    }
    a.x += a2.x; a.y += a2.y; a.z += a2.z; a.w += a2.w;
    *(float4*)(tout + (size_t)n * 64 + q * 4) =
        make_float4(fmaxf(a.x, 0.f), fmaxf(a.y, 0.f), fmaxf(a.z, 0.f), fmaxf(a.w, 0.f));
}

// -------- fused: h = relu(t@W2+b2); pool h per-graph into pcat; y = h@W1n fp16 (if SECOND) --------
template<bool SECOND>
__global__ void __launch_bounds__(256) mlp2_kernel(
    const float* __restrict__ tin,
    const float* __restrict__ W2, const float* __restrict__ b2,
    const int* __restrict__ batch, int layer,
    const float* __restrict__ W1n, __half* __restrict__ yout)
{
    extern __shared__ float sm[];
    float* zs = sm;              // [64][65]
    float* w2 = zs + 64 * 65;    // [64][64]
    float* hs = w2 + 4096;       // [64][65]  (h transposed [c][n])
    float* w1 = hs + 64 * 65;    // [64][64]
    int*   sb = (int*)(w1 + 4096); // [64] batch ids
    int tid = threadIdx.x;
    int node0 = blockIdx.x * 64;
    int nmax = min(64, NN - node0);

    for (int i = tid; i < 4096; i += 256) {
        w2[i] = W2[i];
        if (SECOND) w1[i] = W1n[i];
    }
    if (tid < 64) sb[tid] = (tid < nmax) ? batch[node0 + tid] : -1;
    for (int i = tid; i < 1024; i += 256) {    // 64 nodes x 16 float4
        int n = i >> 4, kq = i & 15;
        int gn = node0 + n;
        float4 v = (gn < NN) ? *(const float4*)(tin + (size_t)gn * 64 + kq * 4)
                             : make_float4(0.f, 0.f, 0.f, 0.f);
        zs[(4 * kq + 0) * 65 + n] = v.x;
        zs[(4 * kq + 1) * 65 + n] = v.y;
        zs[(4 * kq + 2) * 65 + n] = v.z;
        zs[(4 * kq + 3) * 65 + n] = v.w;
    }
    __syncthreads();

    int n = tid & 63, grp = tid >> 6, cb = grp * 16;
    int gn = node0 + n;

    // ---- GEMM 1: h = relu(t @ W2 + b2) ----
    u64 acc[8];
#pragma unroll
    for (int j = 0; j < 8; j++) acc[j] = pack2(b2[cb + 2 * j], b2[cb + 2 * j + 1]);
    for (int k = 0; k < 64; k++) {
        u64 zz = dup2(zs[k * 65 + n]);
        const ulonglong2* wr = (const ulonglong2*)&w2[k * 64 + cb];
#pragma unroll
        for (int j = 0; j < 4; j++) {
            ulonglong2 w = wr[j];
            fma2(acc[2 * j], zz, w.x);
            fma2(acc[2 * j + 1], zz, w.y);
        }
    }
#pragma unroll
    for (int j = 0; j < 8; j++) {
        float2 a = unpack2(acc[j]);
        hs[(cb + 2 * j) * 65 + n]     = fmaxf(a.x, 0.f);
        hs[(cb + 2 * j + 1) * 65 + n] = fmaxf(a.y, 0.f);
    }
    __syncthreads();

    // ---- pooling: per-graph partial sums of h into pcat (batch is sorted) ----
    {
        int c = tid & 63;          // channel
        int q = tid >> 6;          // node chunk
        int i0 = q * 16;
        if (i0 < nmax) {
            int iend = min(i0 + 16, nmax);
            int cur = sb[i0];
            float s = 0.f;
            for (int i = i0; i < iend; i++) {
                int b = sb[i];
                if (b != cur) {
                    red_f32(&g_pcat[cur * 256 + layer * 64 + c], s);
                    s = 0.f;
                    cur = b;
                }
                s += hs[c * 65 + i];
            }
            red_f32(&g_pcat[cur * 256 + layer * 64 + c], s);
        }
    }

    // ---- GEMM 2: y = h @ W1_next (fp16 output) ----
    if (!SECOND) return;
    u64 a2[8];
#pragma unroll
    for (int j = 0; j < 8; j++) a2[j] = 0ull;
    for (int k = 0; k < 64; k++) {
        u64 zz = dup2(hs[k * 65 + n]);
        const ulonglong2* wr = (const ulonglong2*)&w1[k * 64 + cb];
#pragma unroll
        for (int j = 0; j < 4; j++) {
            ulonglong2 w = wr[j];
            fma2(a2[2 * j], zz, w.x);
            fma2(a2[2 * j + 1], zz, w.y);
        }
    }
    if (gn < NN) {
        uint4 o0, o1;
        o0.x = f32x2_to_h2(a2[0]);
        o0.y = f32x2_to_h2(a2[1]);
        o0.z = f32x2_to_h2(a2[2]);
        o0.w = f32x2_to_h2(a2[3]);
        o1.x = f32x2_to_h2(a2[4]);
        o1.y = f32x2_to_h2(a2[5]);
        o1.z = f32x2_to_h2(a2[6]);
        o1.w = f32x2_to_h2(a2[7]);
        uint4* o = (uint4*)(yout + (size_t)gn * 64 + cb);
        o[0] = o0;
        o[1] = o1;
    }
}

// ---------------- JK projection on pooled ----------------
__global__ void __launch_bounds__(64) proj_kernel(
    const float* __restrict__ Wjk, const float* __restrict__ bjk)
{
    __shared__ float ps[256];
    int g = blockIdx.x, c = threadIdx.x;
    for (int i = c; i < 256; i += 64) ps[i] = g_pcat[g * 256 + i];
    __syncthreads();
    float acc = (float)g_cnt[g] * bjk[c];
    for (int k = 0; k < 256; k++) acc += ps[k] * Wjk[k * 64 + c];
    g_pooled[g * 64 + c] = acc;
}

// ---------------- classifier ----------------
__global__ void __launch_bounds__(128) classifier_kernel(
    const float* __restrict__ Wc1, const float* __restrict__ bc1,
    const float* __restrict__ gamma, const float* __restrict__ beta,
    const float* __restrict__ Wc2, const float* __restrict__ bc2,
    float* __restrict__ out)
{
    extern __shared__ float sm[];
    float* W1s = sm;                  // [64][64]
    float* zsm = W1s + 64 * 64;       // [64][129]
    float* scale_s = zsm + 64 * 129;
    float* shift_s = scale_s + 64;

    int tid = threadIdx.x;
    for (int i = tid; i < 64 * 64; i += 128) W1s[i] = Wc1[i];
    __syncthreads();

    float acc[64];
#pragma unroll
    for (int c = 0; c < 64; c++) acc[c] = bc1[c];
    for (int k = 0; k < 64; k++) {
        float pk = g_pooled[tid * 64 + k];
#pragma unroll
        for (int c = 0; c < 64; c++) acc[c] += pk * W1s[k * 64 + c];
    }
#pragma unroll
    for (int c = 0; c < 64; c++) zsm[c * 129 + tid] = acc[c];
    __syncthreads();

    if (tid < 64) {
        int c = tid;
        float s = 0.f;
        for (int g = 0; g < GNUM; g++) s += zsm[c * 129 + g];
        float mu = s / GNUM;
        float v = 0.f;
        for (int g = 0; g < GNUM; g++) {
            float d = zsm[c * 129 + g] - mu;
            v += d * d;
        }
        v /= GNUM;
        float sc = gamma[c] * rsqrtf(v + 1e-5f);
        scale_s[c] = sc;
        shift_s[c] = beta[c] - mu * sc;
    }
    __syncthreads();

    float o[OUT_CH];
#pragma unroll
    for (int j = 0; j < OUT_CH; j++) o[j] = bc2[j];
    for (int c = 0; c < 64; c++) {
        float zn = fmaxf(zsm[c * 129 + tid] * scale_s[c] + shift_s[c], 0.f);
#pragma unroll
        for (int j = 0; j < OUT_CH; j++) o[j] += zn * Wc2[c * OUT_CH + j];
    }
#pragma unroll
    for (int j = 0; j < OUT_CH; j++) out[tid * OUT_CH + j] = o[j];
}

// ---------------- launch ----------------
extern "C" void kernel_launch(void* const* d_in, const int* in_sizes, int n_in,
                              void* d_out, int out_size)
{
    const float* x     = (const float*)d_in[0];
    const int*   ei    = (const int*)d_in[1];
    const int*   batch = (const int*)d_in[2];
    const float* W1f = (const float*)d_in[3];
    const float* b1f = (const float*)d_in[4];
    const float* W2f = (const float*)d_in[5];
    const float* b2f = (const float*)d_in[6];
    const float* W1r = (const float*)d_in[7];
    const float* b1r = (const float*)d_in[8];
    const float* W2r = (const float*)d_in[9];
    const float* b2r = (const float*)d_in[10];
    const float* Wjk = (const float*)d_in[11];
    const float* bjk = (const float*)d_in[12];
    const float* Wc1 = (const float*)d_in[13];
    const float* bc1 = (const float*)d_in[14];
    const float* gm  = (const float*)d_in[15];
    const float* bt  = (const float*)d_in[16];
    const float* Wc2 = (const float*)d_in[17];
    const float* bc2 = (const float*)d_in[18];
    float* out = (float*)d_out;

    void *p_deg, *p_pcat, *p_cnt, *p_y, *p_t;
    cudaGetSymbolAddress(&p_deg, g_deg);
    cudaGetSymbolAddress(&p_pcat, g_pcat);
    cudaGetSymbolAddress(&p_cnt, g_cnt);
    cudaGetSymbolAddress(&p_y, g_y);
    cudaGetSymbolAddress(&p_t, g_t);
    __half* y = (__half*)p_y;
    float*  t = (float*)p_t;

    const size_t SM_Y0  = (128 * 65 + 128 * 64) * sizeof(float);                 // 66048
    const size_t SM_MLP = (64 * 65 * 2 + 4096 * 2) * sizeof(float) + 64 * 4;     // 66304
    const size_t SM_CLS = (64 * 64 + 64 * 129 + 128) * sizeof(float);            // 49920

    cudaFuncSetAttribute(gemm_y0_kernel, cudaFuncAttributeMaxDynamicSharedMemorySize, (int)SM_Y0);
    cudaFuncSetAttribute(mlp2_kernel<true>,  cudaFuncAttributeMaxDynamicSharedMemorySize, (int)SM_MLP);
    cudaFuncSetAttribute(mlp2_kernel<false>, cudaFuncAttributeMaxDynamicSharedMemorySize, (int)SM_MLP);
    cudaFuncSetAttribute(classifier_kernel, cudaFuncAttributeMaxDynamicSharedMemorySize, (int)SM_CLS);

    const int EB = (NE + 255) / 256;       // 6250
    const int SB = (NN + 1023) / 1024;     // 98
    const int GB64 = (NN + 63) / 64;       // 1563
    const int GB16 = (NN + 15) / 16;       // 6250

    // fork a side stream for the CSR build (capture-legal event fork/join)
    cudaStream_t s1;
    cudaStreamCreateWithFlags(&s1, cudaStreamNonBlocking);
    cudaEvent_t evFork, evJoin;
    cudaEventCreateWithFlags(&evFork, cudaEventDisableTiming);
    cudaEventCreateWithFlags(&evJoin, cudaEventDisableTiming);

    cudaEventRecord(evFork, 0);
    cudaStreamWaitEvent(s1, evFork, 0);

    // --- side stream: CSR build + graph counts ---
    cudaMemsetAsync(p_deg, 0, NN * sizeof(int), s1);
    cudaMemsetAsync(p_cnt, 0, GNUM * sizeof(int), s1);
    hist_kernel<<<EB, 256, 0, s1>>>(ei);
    scan1_kernel<<<SB, 256, 0, s1>>>();
    scan2_kernel<<<1, 128, 0, s1>>>(SB);
    scan3_kernel<<<SB, 256, 0, s1>>>();
    fill_kernel<<<EB, 256, 0, s1>>>(ei);
    cnt_kernel<<<(NN + 255) / 256, 256, 0, s1>>>(batch);
    cudaEventRecord(evJoin, s1);

    // --- main stream: pcat zero + y0 = x @ W1f (overlaps CSR build) ---
    cudaMemsetAsync(p_pcat, 0, GNUM * 256 * sizeof(float), 0);
    gemm_y0_kernel<<<GB64, 256, SM_Y0>>>(x, W1f);

    // join
    cudaStreamWaitEvent(0, evJoin, 0);

    // --- layers: gather (y -> t), then fused MLP+pool (t -> y) ---
    for (int l = 0; l < 4; l++) {
        const float* b1 = (l == 0) ? b1f : b1r + (size_t)(l - 1) * 64;
        const float* W2 = (l == 0) ? W2f : W2r + (size_t)(l - 1) * 4096;
        const float* b2 = (l == 0) ? b2f : b2r + (size_t)(l - 1) * 64;
        gather_kernel<<<GB16, 256>>>(y, b1, t);
        if (l < 3) {
            const float* W1n = W1r + (size_t)l * 4096;
            mlp2_kernel<true><<<GB64, 256, SM_MLP>>>(t, W2, b2, batch, l, W1n, y);
        } else {
            mlp2_kernel<false><<<GB64, 256, SM_MLP>>>(t, W2, b2, batch, l, nullptr, nullptr);
        }
    }

    // --- JK projection + classifier ---
    proj_kernel<<<GNUM, 64>>>(Wjk, bjk);
    classifier_kernel<<<1, 128, SM_CLS>>>(Wc1, bc1, gm, bt, Wc2, bc2, out);
}

// round 16
// speedup vs baseline: 1.2913x; 1.0162x over previous
#include <cuda_runtime.h>
#include <cuda_fp16.h>
#include <cstdint>

#define NN 100000
#define NE 1600000
#define GNUM 128
#define OUT_CH 10

typedef unsigned long long u64;

// ---------------- device scratch ----------------
__device__ int    g_deg[NN];
__device__ int    g_rowptr[NN + 1];
__device__ int    g_cursor[NN];
__device__ int    g_esrc[NE];
__device__ int    g_bsum[128];
__device__ __half g_y[(size_t)NN * 64];          // fp16 message table (128 B/row)
__device__ __half g_y2[(size_t)NN * 64];         // ping-pong partner
__device__ float  g_pcat[GNUM * 256];            // k = layer*64 + c
__device__ int    g_cnt[GNUM];
__device__ float  g_pooled[GNUM * 64];

// ---------------- f32x2 helpers ----------------
__device__ __forceinline__ u64 pack2(float lo, float hi) {
    u64 r; asm("mov.b64 %0, {%1, %2};" : "=l"(r) : "f"(lo), "f"(hi)); return r;
}
__device__ __forceinline__ u64 dup2(float v) {
    u64 r; asm("mov.b64 %0, {%1, %1};" : "=l"(r) : "f"(v)); return r;
}
__device__ __forceinline__ void fma2(u64& d, u64 a, u64 b) {
    asm("fma.rn.f32x2 %0, %1, %2, %0;" : "+l"(d) : "l"(a), "l"(b));
}
__device__ __forceinline__ float2 unpack2(u64 v) {
    float2 f; asm("mov.b64 {%0, %1}, %2;" : "=f"(f.x), "=f"(f.y) : "l"(v)); return f;
}
__device__ __forceinline__ unsigned int f32x2_to_h2(u64 v) {
    float2 f = unpack2(v);
    unsigned int r;
    asm("cvt.rn.f16x2.f32 %0, %1, %2;" : "=r"(r) : "f"(f.y), "f"(f.x));
    return r;
}
__device__ __forceinline__ void red_f32(float* p, float v) {
    asm volatile("red.global.add.f32 [%0], %1;" :: "l"(p), "f"(v) : "memory");
}
__device__ __forceinline__ void h2acc(float* a, uint4 v) {
    float2 f;
    f = __half22float2(*(const __half2*)&v.x); a[0] += f.x; a[1] += f.y;
    f = __half22float2(*(const __half2*)&v.y); a[2] += f.x; a[3] += f.y;
    f = __half22float2(*(const __half2*)&v.z); a[4] += f.x; a[5] += f.y;
    f = __half22float2(*(const __half2*)&v.w); a[6] += f.x; a[7] += f.y;
}

// ---------------- CSR build ----------------
__global__ void hist_kernel(const int* __restrict__ ei) {
    int e = blockIdx.x * blockDim.x + threadIdx.x;
    if (e < NE) atomicAdd(&g_deg[ei[NE + e]], 1);
}

__global__ void scan1_kernel() {
    __shared__ int wsum[8];
    int tid = threadIdx.x;
    int base = blockIdx.x * 1024 + tid * 4;
    int v[4];
#pragma unroll
    for (int i = 0; i < 4; i++) v[i] = (base + i < NN) ? g_deg[base + i] : 0;
    int s = v[0] + v[1] + v[2] + v[3];
    int lane = tid & 31, w = tid >> 5;
    int inc = s;
    for (int o = 1; o < 32; o <<= 1) {
        int t = __shfl_up_sync(0xffffffffu, inc, o);
        if (lane >= o) inc += t;
    }
    if (lane == 31) wsum[w] = inc;
    __syncthreads();
    if (tid < 8) {
        int x = wsum[tid];
        int inc2 = x;
        for (int o = 1; o < 8; o <<= 1) {
            int t = __shfl_up_sync(0xffu, inc2, o);
            if (tid >= o) inc2 += t;
        }
        wsum[tid] = inc2 - x;
        if (tid == 7) g_bsum[blockIdx.x] = inc2;
    }
    __syncthreads();
    int run = wsum[w] + inc - s;
#pragma unroll
    for (int i = 0; i < 4; i++) {
        if (base + i < NN) g_deg[base + i] = run;
        run += v[i];
    }
}

__global__ void scan2_kernel(int nb) {
    __shared__ int ws[4];
    int tid = threadIdx.x;
    int v = (tid < nb) ? g_bsum[tid] : 0;
    int lane = tid & 31, w = tid >> 5;
    int inc = v;
    for (int o = 1; o < 32; o <<= 1) {
        int t = __shfl_up_sync(0xffffffffu, inc, o);
        if (lane >= o) inc += t;
    }
    if (lane == 31) ws[w] = inc;
    __syncthreads();
    int add = 0;
    for (int i = 0; i < w; i++) add += ws[i];
    if (tid < nb) g_bsum[tid] = add + inc - v;
}

__global__ void scan3_kernel() {
    int tid = threadIdx.x;
    int base = blockIdx.x * 1024 + tid * 4;
    int add = g_bsum[blockIdx.x];
#pragma unroll
    for (int i = 0; i < 4; i++) {
        int idx = base + i;
        if (idx < NN) {
            int r = g_deg[idx] + add;
            g_rowptr[idx] = r;
            g_cursor[idx] = r;
        }
    }
    if (blockIdx.x == 0 && tid == 0) g_rowptr[NN] = NE;
}

__global__ void fill_kernel(const int* __restrict__ ei) {
    int e = blockIdx.x * blockDim.x + threadIdx.x;
    if (e < NE) {
        int d = ei[NE + e];
        int p = atomicAdd(&g_cursor[d], 1);
        g_esrc[p] = ei[e];
    }
}

// ---------------- graph counts ----------------
__global__ void cnt_kernel(const int* __restrict__ batch) {
    __shared__ int h[GNUM];
    int tid = threadIdx.x;
    if (tid < GNUM) h[tid] = 0;
    __syncthreads();
    int i = blockIdx.x * 256 + tid;
    if (i < NN) atomicAdd(&h[batch[i]], 1);
    __syncthreads();
    if (tid < GNUM && h[tid]) atomicAdd(&g_cnt[tid], h[tid]);
}

// ---------------- y0 = x @ W1f (K=128 -> 64), f32x2, fp16 output ----------------
__global__ void __launch_bounds__(256) gemm_y0_kernel(
    const float* __restrict__ x, const float* __restrict__ W)
{
    extern __shared__ float sm[];
    float* zs = sm;            // [128][65]
    float* ws = zs + 128 * 65; // [128][64]
    int tid = threadIdx.x;
    int node0 = blockIdx.x * 64;

    for (int i = tid; i < 128 * 64; i += 256) ws[i] = W[i];
    for (int i = tid; i < 2048; i += 256) {     // 64 nodes x 32 float4
        int n = i >> 5, kq = i & 31;
        int gn = node0 + n;
        float4 v = (gn < NN) ? *(const float4*)(x + (size_t)gn * 128 + kq * 4)
                             : make_float4(0.f, 0.f, 0.f, 0.f);
        zs[(4 * kq + 0) * 65 + n] = v.x;
        zs[(4 * kq + 1) * 65 + n] = v.y;
        zs[(4 * kq + 2) * 65 + n] = v.z;
        zs[(4 * kq + 3) * 65 + n] = v.w;
    }
    __syncthreads();

    int n = tid & 63, grp = tid >> 6, cb = grp * 16;
    u64 acc[8];
#pragma unroll
    for (int j = 0; j < 8; j++) acc[j] = 0ull;
    for (int k = 0; k < 128; k++) {
        u64 zz = dup2(zs[k * 65 + n]);
        const ulonglong2* wr = (const ulonglong2*)&ws[k * 64 + cb];
#pragma unroll
        for (int j = 0; j < 4; j++) {
            ulonglong2 w = wr[j];
            fma2(acc[2 * j], zz, w.x);
            fma2(acc[2 * j + 1], zz, w.y);
        }
    }
    int gn = node0 + n;
    if (gn < NN) {
        uint4 o0, o1;
        o0.x = f32x2_to_h2(acc[0]);
        o0.y = f32x2_to_h2(acc[1]);
        o0.z = f32x2_to_h2(acc[2]);
        o0.w = f32x2_to_h2(acc[3]);
        o1.x = f32x2_to_h2(acc[4]);
        o1.y = f32x2_to_h2(acc[5]);
        o1.z = f32x2_to_h2(acc[6]);
        o1.w = f32x2_to_h2(acc[7]);
        uint4* o = (uint4*)(g_y + (size_t)gn * 64 + cb);
        o[0] = o0;
        o[1] = o1;
    }
}

// -------- fused layer: gather z = relu(y + Σ y[src] + b1) (8 thr/node, fp16 y);
//          h = relu(z@W2+b2); pool h into pcat; yout = h@W1n fp16 (if SECOND) --------
// 256 threads, 32 nodes/block, ~50 KB smem -> 4 CTAs/SM.
template<bool SECOND>
__global__ void __launch_bounds__(256, 4) layer_kernel(
    const __half* __restrict__ y, const float* __restrict__ b1,
    const float* __restrict__ W2, const float* __restrict__ b2,
    const int* __restrict__ batch, int layer,
    const float* __restrict__ W1n, __half* __restrict__ yout)
{
    extern __shared__ float sm[];
    float* zs = sm;              // [64][33]  (z transposed [k][n])
    float* w2 = zs + 64 * 33;    // [64][64]
    float* hs = w2 + 4096;       // [64][33]  (h transposed [c][n])
    float* w1 = hs + 64 * 33;    // [64][64]
    int*   sb = (int*)(w1 + 4096); // [32] batch ids
    int tid = threadIdx.x;
    int node0 = blockIdx.x * 32;
    int nmax = min(32, NN - node0);

    for (int i = tid; i < 4096; i += 256) {
        w2[i] = W2[i];
        if (SECOND) w1[i] = W1n[i];
    }
    if (tid < 32) sb[tid] = (tid < nmax) ? batch[node0 + tid] : -1;

    // ---- gather: 8 threads/node, 8 channels each (16 B = full fp16 row across 8 thr) ----
    {
        int n = tid >> 3;          // 0..31
        int q = tid & 7;           // uint4 chunk within 128-B row
        int gn = node0 + n;
        float a[8], b[8];
#pragma unroll
        for (int i = 0; i < 8; i++) { a[i] = 0.f; b[i] = 0.f; }
        if (gn < NN) {
            const uint4* yb = (const uint4*)y;      // row = 8 uint4
            h2acc(a, yb[(size_t)gn * 8 + q]);
#pragma unroll
            for (int i = 0; i < 8; i++) a[i] += b1[q * 8 + i];
            int beg = g_rowptr[gn], end = g_rowptr[gn + 1];
            int e = beg;
            for (; e + 1 < end; e += 2) {
                int s0 = g_esrc[e];
                int s1 = g_esrc[e + 1];
                uint4 v0 = yb[(size_t)s0 * 8 + q];
                uint4 v1 = yb[(size_t)s1 * 8 + q];
                h2acc(a, v0);
                h2acc(b, v1);
            }
            if (e < end) h2acc(a, yb[(size_t)g_esrc[e] * 8 + q]);
        }
#pragma unroll
        for (int i = 0; i < 8; i++)
            zs[(q * 8 + i) * 33 + n] = fmaxf(a[i] + b[i], 0.f);
    }
    __syncthreads();

    int n = tid & 31, grp = tid >> 5, cb = grp * 8;
    int gn = node0 + n;

    // ---- GEMM 1: h = relu(z @ W2 + b2), 8 outputs/thread ----
    u64 acc[4];
#pragma unroll
    for (int j = 0; j < 4; j++) acc[j] = pack2(b2[cb + 2 * j], b2[cb + 2 * j + 1]);
    for (int k = 0; k < 64; k++) {
        u64 zz = dup2(zs[k * 33 + n]);
        const ulonglong2* wr = (const ulonglong2*)&w2[k * 64 + cb];
        ulonglong2 wa = wr[0], wb = wr[1];
        fma2(acc[0], zz, wa.x);
        fma2(acc[1], zz, wa.y);
        fma2(acc[2], zz, wb.x);
        fma2(acc[3], zz, wb.y);
    }
#pragma unroll
    for (int j = 0; j < 4; j++) {
        float2 a = unpack2(acc[j]);
        hs[(cb + 2 * j) * 33 + n]     = fmaxf(a.x, 0.f);
        hs[(cb + 2 * j + 1) * 33 + n] = fmaxf(a.y, 0.f);
    }
    __syncthreads();

    // ---- pooling: per-graph partial sums of h into pcat (batch is sorted) ----
    {
        int c = tid & 63;          // channel
        int q = tid >> 6;          // node chunk (4 chunks of 8)
        int i0 = q * 8;
        if (i0 < nmax) {
            int iend = min(i0 + 8, nmax);
            int cur = sb[i0];
            float s = 0.f;
            for (int i = i0; i < iend; i++) {
                int b = sb[i];
                if (b != cur) {
                    red_f32(&g_pcat[cur * 256 + layer * 64 + c], s);
                    s = 0.f;
                    cur = b;
                }
                s += hs[c * 33 + i];
            }
            red_f32(&g_pcat[cur * 256 + layer * 64 + c], s);
        }
    }

    // ---- GEMM 2: yout = h @ W1_next (fp16 output, OTHER buffer; no race) ----
    if (!SECOND) return;
    u64 a2[4];
#pragma unroll
    for (int j = 0; j < 4; j++) a2[j] = 0ull;
    for (int k = 0; k < 64; k++) {
        u64 zz = dup2(hs[k * 33 + n]);
        const ulonglong2* wr = (const ulonglong2*)&w1[k * 64 + cb];
        ulonglong2 wa = wr[0], wb = wr[1];
        fma2(a2[0], zz, wa.x);
        fma2(a2[1], zz, wa.y);
        fma2(a2[2], zz, wb.x);
        fma2(a2[3], zz, wb.y);
    }
    if (gn < NN) {
        uint4 o;
        o.x = f32x2_to_h2(a2[0]);
        o.y = f32x2_to_h2(a2[1]);
        o.z = f32x2_to_h2(a2[2]);
        o.w = f32x2_to_h2(a2[3]);
        *(uint4*)(yout + (size_t)gn * 64 + cb) = o;
    }
}

// ---------------- JK projection on pooled ----------------
__global__ void __launch_bounds__(64) proj_kernel(
    const float* __restrict__ Wjk, const float* __restrict__ bjk)
{
    __shared__ float ps[256];
    int g = blockIdx.x, c = threadIdx.x;
    for (int i = c; i < 256; i += 64) ps[i] = g_pcat[g * 256 + i];
    __syncthreads();
    float acc = (float)g_cnt[g] * bjk[c];
    for (int k = 0; k < 256; k++) acc += ps[k] * Wjk[k * 64 + c];
    g_pooled[g * 64 + c] = acc;
}

// ---------------- classifier ----------------
__global__ void __launch_bounds__(128) classifier_kernel(
    const float* __restrict__ Wc1, const float* __restrict__ bc1,
    const float* __restrict__ gamma, const float* __restrict__ beta,
    const float* __restrict__ Wc2, const float* __restrict__ bc2,
    float* __restrict__ out)
{
    extern __shared__ float sm[];
    float* W1s = sm;                  // [64][64]
    float* zsm = W1s + 64 * 64;       // [64][129]
    float* scale_s = zsm + 64 * 129;
    float* shift_s = scale_s + 64;

    int tid = threadIdx.x;
    for (int i = tid; i < 64 * 64; i += 128) W1s[i] = Wc1[i];
    __syncthreads();

    float acc[64];
#pragma unroll
    for (int c = 0; c < 64; c++) acc[c] = bc1[c];
    for (int k = 0; k < 64; k++) {
        float pk = g_pooled[tid * 64 + k];
#pragma unroll
        for (int c = 0; c < 64; c++) acc[c] += pk * W1s[k * 64 + c];
    }
#pragma unroll
    for (int c = 0; c < 64; c++) zsm[c * 129 + tid] = acc[c];
    __syncthreads();

    if (tid < 64) {
        int c = tid;
        float s = 0.f;
        for (int g = 0; g < GNUM; g++) s += zsm[c * 129 + g];
        float mu = s / GNUM;
        float v = 0.f;
        for (int g = 0; g < GNUM; g++) {
            float d = zsm[c * 129 + g] - mu;
            v += d * d;
        }
        v /= GNUM;
        float sc = gamma[c] * rsqrtf(v + 1e-5f);
        scale_s[c] = sc;
        shift_s[c] = beta[c] - mu * sc;
    }
    __syncthreads();

    float o[OUT_CH];
#pragma unroll
    for (int j = 0; j < OUT_CH; j++) o[j] = bc2[j];
    for (int c = 0; c < 64; c++) {
        float zn = fmaxf(zsm[c * 129 + tid] * scale_s[c] + shift_s[c], 0.f);
#pragma unroll
        for (int j = 0; j < OUT_CH; j++) o[j] += zn * Wc2[c * OUT_CH + j];
    }
#pragma unroll
    for (int j = 0; j < OUT_CH; j++) out[tid * OUT_CH + j] = o[j];
}

// ---------------- launch ----------------
extern "C" void kernel_launch(void* const* d_in, const int* in_sizes, int n_in,
                              void* d_out, int out_size)
{
    const float* x     = (const float*)d_in[0];
    const int*   ei    = (const int*)d_in[1];
    const int*   batch = (const int*)d_in[2];
    const float* W1f = (const float*)d_in[3];
    const float* b1f = (const float*)d_in[4];
    const float* W2f = (const float*)d_in[5];
    const float* b2f = (const float*)d_in[6];
    const float* W1r = (const float*)d_in[7];
    const float* b1r = (const float*)d_in[8];
    const float* W2r = (const float*)d_in[9];
    const float* b2r = (const float*)d_in[10];
    const float* Wjk = (const float*)d_in[11];
    const float* bjk = (const float*)d_in[12];
    const float* Wc1 = (const float*)d_in[13];
    const float* bc1 = (const float*)d_in[14];
    const float* gm  = (const float*)d_in[15];
    const float* bt  = (const float*)d_in[16];
    const float* Wc2 = (const float*)d_in[17];
    const float* bc2 = (const float*)d_in[18];
    float* out = (float*)d_out;

    void *p_deg, *p_pcat, *p_cnt, *p_y, *p_y2;
    cudaGetSymbolAddress(&p_deg, g_deg);
    cudaGetSymbolAddress(&p_pcat, g_pcat);
    cudaGetSymbolAddress(&p_cnt, g_cnt);
    cudaGetSymbolAddress(&p_y, g_y);
    cudaGetSymbolAddress(&p_y2, g_y2);
    __half* ybuf[2] = { (__half*)p_y, (__half*)p_y2 };

    const size_t SM_Y0  = (128 * 65 + 128 * 64) * sizeof(float);                 // 66048
    const size_t SM_LYR = (64 * 33 * 2 + 4096 * 2) * sizeof(float) + 32 * 4;     // 49792
    const size_t SM_CLS = (64 * 64 + 64 * 129 + 128) * sizeof(float);            // 49920

    cudaFuncSetAttribute(gemm_y0_kernel, cudaFuncAttributeMaxDynamicSharedMemorySize, (int)SM_Y0);
    cudaFuncSetAttribute(layer_kernel<true>,  cudaFuncAttributeMaxDynamicSharedMemorySize, (int)SM_LYR);
    cudaFuncSetAttribute(layer_kernel<false>, cudaFuncAttributeMaxDynamicSharedMemorySize, (int)SM_LYR);
    cudaFuncSetAttribute(classifier_kernel, cudaFuncAttributeMaxDynamicSharedMemorySize, (int)SM_CLS);

    const int EB = (NE + 255) / 256;       // 6250
    const int SB = (NN + 1023) / 1024;     // 98
    const int GB64 = (NN + 63) / 64;       // 1563
    const int GB32 = (NN + 31) / 32;       // 3125

    // fork a side stream for the CSR build (capture-legal event fork/join)
    cudaStream_t s1;
    cudaStreamCreateWithFlags(&s1, cudaStreamNonBlocking);
    cudaEvent_t evFork, evJoin;
    cudaEventCreateWithFlags(&evFork, cudaEventDisableTiming);
    cudaEventCreateWithFlags(&evJoin, cudaEventDisableTiming);

    cudaEventRecord(evFork, 0);
    cudaStreamWaitEvent(s1, evFork, 0);

    // --- side stream: CSR build + graph counts ---
    cudaMemsetAsync(p_deg, 0, NN * sizeof(int), s1);
    cudaMemsetAsync(p_cnt, 0, GNUM * sizeof(int), s1);
    hist_kernel<<<EB, 256, 0, s1>>>(ei);
    scan1_kernel<<<SB, 256, 0, s1>>>();
    scan2_kernel<<<1, 128, 0, s1>>>(SB);
    scan3_kernel<<<SB, 256, 0, s1>>>();
    fill_kernel<<<EB, 256, 0, s1>>>(ei);
    cnt_kernel<<<(NN + 255) / 256, 256, 0, s1>>>(batch);
    cudaEventRecord(evJoin, s1);

    // --- main stream: pcat zero + y0 = x @ W1f (overlaps CSR build) ---
    cudaMemsetAsync(p_pcat, 0, GNUM * 256 * sizeof(float), 0);
    gemm_y0_kernel<<<GB64, 256, SM_Y0>>>(x, W1f);

    // join
    cudaStreamWaitEvent(0, evJoin, 0);

    // --- fused layers (ping-pong fp16 y buffers) ---
    for (int l = 0; l < 4; l++) {
        const float* b1 = (l == 0) ? b1f : b1r + (size_t)(l - 1) * 64;
        const float* W2 = (l == 0) ? W2f : W2r + (size_t)(l - 1) * 4096;
        const float* b2 = (l == 0) ? b2f : b2r + (size_t)(l - 1) * 64;
        const __half* yin = ybuf[l & 1];
        __half* yo = ybuf[(l + 1) & 1];
        if (l < 3) {
            const float* W1n = W1r + (size_t)l * 4096;
            layer_kernel<true><<<GB32, 256, SM_LYR>>>(yin, b1, W2, b2, batch, l, W1n, yo);
        } else {
            layer_kernel<false><<<GB32, 256, SM_LYR>>>(yin, b1, W2, b2, batch, l, nullptr, nullptr);
        }
    }

    // --- JK projection + classifier ---
    proj_kernel<<<GNUM, 64>>>(Wjk, bjk);
    classifier_kernel<<<1, 128, SM_CLS>>>(Wc1, bc1, gm, bt, Wc2, bc2, out);
}